// round 5
// baseline (speedup 1.0000x reference)
#include <cuda_runtime.h>
#include <cuda_bf16.h>
#include <cstdint>

#define DINLINE __device__ __forceinline__

// ---------------- device scratch (no dynamic alloc allowed) ----------------
static __device__ __align__(16) __nv_bfloat16 g_xh[8192 * 1024];
static __device__ __align__(16) __nv_bfloat16 g_xl[8192 * 1024];
static __device__ __align__(16) __nv_bfloat16 g_fh[3072 * 1024];
static __device__ __align__(16) __nv_bfloat16 g_fl[3072 * 1024];

// ---------------- portable PTX helpers (sm_80-class ISA only) ----------------
DINLINE uint32_t smem_u32(const void* p) {
    uint32_t a;
    asm("{ .reg .u64 t; cvta.to.shared.u64 t, %1; cvt.u32.u64 %0, t; }" : "=r"(a) : "l"(p));
    return a;
}
DINLINE void cp_async16(uint32_t dst, const void* src) {
    asm volatile("cp.async.cg.shared.global [%0], [%1], 16;" :: "r"(dst), "l"(src) : "memory");
}
DINLINE void cp_commit() { asm volatile("cp.async.commit_group;" ::: "memory"); }
DINLINE void cp_wait0() { asm volatile("cp.async.wait_group 0;" ::: "memory"); }
DINLINE void cp_wait1() { asm volatile("cp.async.wait_group 1;" ::: "memory"); }

DINLINE void ldsm4(uint32_t& r0, uint32_t& r1, uint32_t& r2, uint32_t& r3, uint32_t addr) {
    asm volatile("ldmatrix.sync.aligned.m8n8.x4.shared.b16 {%0,%1,%2,%3}, [%4];"
                 : "=r"(r0), "=r"(r1), "=r"(r2), "=r"(r3) : "r"(addr));
}
DINLINE void mma_bf16(float* c, const uint32_t* a, const uint32_t* b) {
    asm volatile(
        "mma.sync.aligned.m16n8k16.row.col.f32.bf16.bf16.f32 "
        "{%0,%1,%2,%3}, {%4,%5,%6,%7}, {%8,%9}, {%0,%1,%2,%3};"
        : "+f"(c[0]), "+f"(c[1]), "+f"(c[2]), "+f"(c[3])
        : "r"(a[0]), "r"(a[1]), "r"(a[2]), "r"(a[3]), "r"(b[0]), "r"(b[1]));
}

DINLINE uint32_t pack_bf2(__nv_bfloat16 a, __nv_bfloat16 b) {
    __nv_bfloat162 t = __halves2bfloat162(a, b);
    return *reinterpret_cast<uint32_t*>(&t);
}
DINLINE void split1(float v, __nv_bfloat16& h, __nv_bfloat16& l) {
    h = __float2bfloat16(v);
    l = __float2bfloat16(v - __bfloat162float(h));
}

// ==================== kernel 1: split x into bf16 hi/lo ====================
__global__ void __launch_bounds__(256) split_x_kernel(const float4* __restrict__ x4) {
    int i = blockIdx.x * 256 + threadIdx.x;   // 2,097,152 float4s total
    float4 v = x4[i];
    __nv_bfloat16 h0, h1, h2, h3, l0, l1, l2, l3;
    split1(v.x, h0, l0); split1(v.y, h1, l1); split1(v.z, h2, l2); split1(v.w, h3, l3);
    reinterpret_cast<uint2*>(g_xh)[i] = make_uint2(pack_bf2(h0, h1), pack_bf2(h2, h3));
    reinterpret_cast<uint2*>(g_xl)[i] = make_uint2(pack_bf2(l0, l1), pack_bf2(l2, l3));
}

// ==================== kernel 2: rotate W, split into bf16 hi/lo ====================
// filt[o, r*128+j] = sum_i W[o, r*128+i] * R_sel[r, i, j]
__global__ void __launch_bounds__(256) rotate_split_kernel(
    const float* __restrict__ W, const float* __restrict__ qR,
    const float* __restrict__ kR, const float* __restrict__ vR) {
    __shared__ float sW[64][128];
    int o0 = blockIdx.x * 64;          // 48 o-tiles
    int r  = blockIdx.y;               // 8 blocks
    int tx = threadIdx.x;              // j: 0..127
    int ty = threadIdx.y;              // 0..1
    int tid = ty * 128 + tx;

    for (int idx = tid; idx < 64 * 128; idx += 256) {
        int row = idx >> 7, i = idx & 127;
        sW[row][i] = W[(size_t)(o0 + row) * 1024 + r * 128 + i];
    }
    __syncthreads();

    const float* R = ((o0 < 1024) ? qR : (o0 < 2048) ? kR : vR) + (size_t)r * 16384;

    float acc[32];
#pragma unroll
    for (int oo = 0; oo < 32; oo++) acc[oo] = 0.0f;

#pragma unroll 4
    for (int i4 = 0; i4 < 32; i4++) {
        float r0 = R[(i4 * 4 + 0) * 128 + tx];
        float r1 = R[(i4 * 4 + 1) * 128 + tx];
        float r2 = R[(i4 * 4 + 2) * 128 + tx];
        float r3 = R[(i4 * 4 + 3) * 128 + tx];
#pragma unroll
        for (int oo = 0; oo < 32; oo++) {
            float4 w = *reinterpret_cast<const float4*>(&sW[ty * 32 + oo][i4 * 4]);
            acc[oo] = fmaf(w.x, r0, fmaf(w.y, r1, fmaf(w.z, r2, fmaf(w.w, r3, acc[oo]))));
        }
    }

#pragma unroll
    for (int oo = 0; oo < 32; oo++) {
        int o = o0 + ty * 32 + oo;
        __nv_bfloat16 h, l;
        split1(acc[oo], h, l);
        size_t off = (size_t)o * 1024 + r * 128 + tx;
        g_fh[off] = h;
        g_fl[off] = l;
    }
}

// ==================== kernel 3: HMMA GEMM, 3-term bf16 split ====================
// out[8192,3072] = Xh*Fh^T + Xh*Fl^T + Xl*Fh^T + bias
//
// BM=128, BN=128, BK=32, 3-stage cp.async pipeline.
// smem per stage: Ah, Al, Bh, Bl each 128 rows x 64B (swizzled) = 4 x 8KB = 32KB.
// XOR swizzle: 16B-chunk c' = c ^ ((row>>1)&3) -> conflict-free cp.async stores
// and conflict-free ldmatrix reads (verified: 8-lane phases cover distinct banks).
static constexpr int BM = 128, BN = 128, BK = 32;
static constexpr int NCHUNKS = 1024 / BK;       // 32
static constexpr int STAGE_BYTES = 32768;
static constexpr int SMEM_SIZE = 3 * STAGE_BYTES;

DINLINE uint32_t swz(int row, int chunk) {            // byte offset within one 8KB array
    return (uint32_t)(row * 64 + (chunk ^ ((row >> 1) & 3)) * 16);
}

DINLINE void load_stage(uint32_t sbase, int m0, int n0, int k0, int tid) {
    // 4 arrays x 128 rows x 4 chunks = 2048 cp.async / 256 threads = 8 each
#pragma unroll
    for (int t = 0; t < 8; t++) {
        int idx = tid + t * 256;
        int arr = idx >> 9;          // 0:Ah 1:Al 2:Bh 3:Bl
        int rem = idx & 511;
        int row = rem >> 2, chunk = rem & 3;
        const __nv_bfloat16* src;
        if (arr == 0)      src = g_xh + (size_t)(m0 + row) * 1024 + k0 + chunk * 8;
        else if (arr == 1) src = g_xl + (size_t)(m0 + row) * 1024 + k0 + chunk * 8;
        else if (arr == 2) src = g_fh + (size_t)(n0 + row) * 1024 + k0 + chunk * 8;
        else               src = g_fl + (size_t)(n0 + row) * 1024 + k0 + chunk * 8;
        cp_async16(sbase + arr * 8192 + swz(row, chunk), src);
    }
}

__global__ void __launch_bounds__(256, 1) gemm_kernel(
    const float* __restrict__ bias, float* __restrict__ out) {
    extern __shared__ __align__(128) char smem[];
    uint32_t sm0 = smem_u32(smem);

    int tid = threadIdx.x;
    int wid = tid >> 5, lane = tid & 31;
    int warp_m = wid & 1;                 // 2 warps in M
    int warp_n = wid >> 1;                // 4 warps in N
    int wm = warp_m * 64;                 // warp tile 64 x 32
    int wn = warp_n * 32;
    int m0 = blockIdx.x * BM;
    int n0 = blockIdx.y * BN;

    // per-lane ldmatrix row/half decomposition
    int a_r    = lane & 15;               // A: lanes 0-15 -> k+0, 16-31 -> k+8
    int a_half = lane >> 4;
    int b_r    = ((lane >> 4) << 3) | (lane & 7);  // B: n-row
    int b_half = (lane >> 3) & 1;                  // k half

    float acc[4][4][4];
#pragma unroll
    for (int i = 0; i < 4; i++)
#pragma unroll
        for (int j = 0; j < 4; j++)
#pragma unroll
            for (int q = 0; q < 4; q++) acc[i][j][q] = 0.0f;

    // prologue: stages 0, 1
    load_stage(sm0, m0, n0, 0, tid); cp_commit();
    load_stage(sm0 + STAGE_BYTES, m0, n0, BK, tid); cp_commit();

    for (int s = 0; s < NCHUNKS; s++) {
        if (s < NCHUNKS - 1) cp_wait1(); else cp_wait0();
        __syncthreads();

        if (s + 2 < NCHUNKS) {
            load_stage(sm0 + ((s + 2) % 3) * STAGE_BYTES, m0, n0, (s + 2) * BK, tid);
            cp_commit();
        }

        uint32_t sb = sm0 + (s % 3) * STAGE_BYTES;
        uint32_t sAh = sb, sAl = sb + 8192, sBh = sb + 16384, sBl = sb + 24576;

#pragma unroll
        for (int kk = 0; kk < 2; kk++) {       // two k16 steps per 32-chunk
            int kb = kk * 2;                   // 16B-chunk base
            uint32_t ah[4][4], al[4][4], bh[2][4], bl[2][4];
#pragma unroll
            for (int mt = 0; mt < 4; mt++) {
                int row = wm + mt * 16 + a_r;
                uint32_t off = swz(row, kb + a_half);
                ldsm4(ah[mt][0], ah[mt][1], ah[mt][2], ah[mt][3], sAh + off);
                ldsm4(al[mt][0], al[mt][1], al[mt][2], al[mt][3], sAl + off);
            }
#pragma unroll
            for (int nt = 0; nt < 2; nt++) {
                int row = wn + nt * 16 + b_r;
                uint32_t off = swz(row, kb + b_half);
                ldsm4(bh[nt][0], bh[nt][1], bh[nt][2], bh[nt][3], sBh + off);
                ldsm4(bl[nt][0], bl[nt][1], bl[nt][2], bl[nt][3], sBl + off);
            }
#pragma unroll
            for (int mt = 0; mt < 4; mt++) {
#pragma unroll
                for (int n8 = 0; n8 < 4; n8++) {
                    const uint32_t* pbh = &bh[n8 >> 1][(n8 & 1) * 2];
                    const uint32_t* pbl = &bl[n8 >> 1][(n8 & 1) * 2];
                    mma_bf16(acc[mt][n8], ah[mt], pbh);   // Ah*Bh
                    mma_bf16(acc[mt][n8], ah[mt], pbl);   // Ah*Bl
                    mma_bf16(acc[mt][n8], al[mt], pbh);   // Al*Bh
                }
            }
        }
    }

    // epilogue: C frag lane mapping: rows l/4, l/4+8; cols (l%4)*2, +1
    int cr = lane >> 2, cc = (lane & 3) * 2;
#pragma unroll
    for (int mt = 0; mt < 4; mt++) {
#pragma unroll
        for (int n8 = 0; n8 < 4; n8++) {
            int col = n0 + wn + n8 * 8 + cc;
            float b0 = __ldg(bias + col), b1 = __ldg(bias + col + 1);
            int row0 = m0 + wm + mt * 16 + cr;
            float2 v0 = make_float2(acc[mt][n8][0] + b0, acc[mt][n8][1] + b1);
            float2 v1 = make_float2(acc[mt][n8][2] + b0, acc[mt][n8][3] + b1);
            *reinterpret_cast<float2*>(out + (size_t)row0 * 3072 + col) = v0;
            *reinterpret_cast<float2*>(out + (size_t)(row0 + 8) * 3072 + col) = v1;
        }
    }
}

// ==================== host ====================
extern "C" void kernel_launch(void* const* d_in, const int* in_sizes, int n_in,
                              void* d_out, int out_size) {
    const float* attn = (const float*)d_in[0];   // [3072, 1024]
    const float* bias = (const float*)d_in[1];   // [3072]
    const float* x    = (const float*)d_in[2];   // [4, 2048, 1024]
    const float* qR   = (const float*)d_in[3];   // [8, 128, 128]
    const float* kR   = (const float*)d_in[4];
    const float* vR   = (const float*)d_in[5];
    float* out = (float*)d_out;                  // [8192, 3072]

    split_x_kernel<<<8192, 256>>>(reinterpret_cast<const float4*>(x));
    rotate_split_kernel<<<dim3(48, 8), dim3(128, 2)>>>(attn, qR, kR, vR);

    cudaFuncSetAttribute(gemm_kernel, cudaFuncAttributeMaxDynamicSharedMemorySize, SMEM_SIZE);
    gemm_kernel<<<dim3(64, 24), 256, SMEM_SIZE>>>(bias, out);
}

// round 6
// speedup vs baseline: 1.5174x; 1.5174x over previous
#include <cuda_runtime.h>
#include <cuda_fp16.h>
#include <cstdint>

#define DINLINE __device__ __forceinline__

// ---------------- device scratch (no dynamic alloc allowed) ----------------
static __device__ __align__(16) __half g_xh[8192 * 1024];
static __device__ __align__(16) __half g_xl[8192 * 1024];
static __device__ __align__(16) __half g_fh[3072 * 1024];

// ---------------- portable PTX helpers (sm_80-class ISA only) ----------------
DINLINE uint32_t smem_u32(const void* p) {
    uint32_t a;
    asm("{ .reg .u64 t; cvta.to.shared.u64 t, %1; cvt.u32.u64 %0, t; }" : "=r"(a) : "l"(p));
    return a;
}
DINLINE void cp_async16(uint32_t dst, const void* src) {
    asm volatile("cp.async.cg.shared.global [%0], [%1], 16;" :: "r"(dst), "l"(src) : "memory");
}
DINLINE void cp_commit() { asm volatile("cp.async.commit_group;" ::: "memory"); }
DINLINE void cp_wait0() { asm volatile("cp.async.wait_group 0;" ::: "memory"); }
DINLINE void cp_wait1() { asm volatile("cp.async.wait_group 1;" ::: "memory"); }

DINLINE void ldsm4(uint32_t* r, uint32_t addr) {
    asm volatile("ldmatrix.sync.aligned.m8n8.x4.shared.b16 {%0,%1,%2,%3}, [%4];"
                 : "=r"(r[0]), "=r"(r[1]), "=r"(r[2]), "=r"(r[3]) : "r"(addr));
}
DINLINE void mma_f16(float* c, const uint32_t* a, const uint32_t* b) {
    asm volatile(
        "mma.sync.aligned.m16n8k16.row.col.f32.f16.f16.f32 "
        "{%0,%1,%2,%3}, {%4,%5,%6,%7}, {%8,%9}, {%0,%1,%2,%3};"
        : "+f"(c[0]), "+f"(c[1]), "+f"(c[2]), "+f"(c[3])
        : "r"(a[0]), "r"(a[1]), "r"(a[2]), "r"(a[3]), "r"(b[0]), "r"(b[1]));
}

DINLINE uint32_t pack_h2(__half a, __half b) {
    __half2 t = __halves2half2(a, b);
    return *reinterpret_cast<uint32_t*>(&t);
}
DINLINE void split1(float v, __half& h, __half& l) {
    h = __float2half(v);
    l = __float2half(v - __half2float(h));
}

// ==================== kernel 1: split x into fp16 hi/lo ====================
__global__ void __launch_bounds__(256) split_x_kernel(const float4* __restrict__ x4) {
    int i = blockIdx.x * 256 + threadIdx.x;   // 2,097,152 float4s total
    float4 v = x4[i];
    __half h0, h1, h2, h3, l0, l1, l2, l3;
    split1(v.x, h0, l0); split1(v.y, h1, l1); split1(v.z, h2, l2); split1(v.w, h3, l3);
    reinterpret_cast<uint2*>(g_xh)[i] = make_uint2(pack_h2(h0, h1), pack_h2(h2, h3));
    reinterpret_cast<uint2*>(g_xl)[i] = make_uint2(pack_h2(l0, l1), pack_h2(l2, l3));
}

// ==================== kernel 2: rotate W -> filt, store fp16 ====================
// filt[o, r*128+j] = sum_i W[o, r*128+i] * R_sel[r, i, j]
__global__ void __launch_bounds__(256) rotate_kernel(
    const float* __restrict__ W, const float* __restrict__ qR,
    const float* __restrict__ kR, const float* __restrict__ vR) {
    __shared__ float sW[64][128];
    int o0 = blockIdx.x * 64;          // 48 o-tiles
    int r  = blockIdx.y;               // 8 blocks
    int tx = threadIdx.x;              // j: 0..127
    int ty = threadIdx.y;              // 0..1
    int tid = ty * 128 + tx;

    for (int idx = tid; idx < 64 * 128; idx += 256) {
        int row = idx >> 7, i = idx & 127;
        sW[row][i] = W[(size_t)(o0 + row) * 1024 + r * 128 + i];
    }
    __syncthreads();

    const float* R = ((o0 < 1024) ? qR : (o0 < 2048) ? kR : vR) + (size_t)r * 16384;

    float acc[32];
#pragma unroll
    for (int oo = 0; oo < 32; oo++) acc[oo] = 0.0f;

#pragma unroll 4
    for (int i4 = 0; i4 < 32; i4++) {
        float r0 = R[(i4 * 4 + 0) * 128 + tx];
        float r1 = R[(i4 * 4 + 1) * 128 + tx];
        float r2 = R[(i4 * 4 + 2) * 128 + tx];
        float r3 = R[(i4 * 4 + 3) * 128 + tx];
#pragma unroll
        for (int oo = 0; oo < 32; oo++) {
            float4 w = *reinterpret_cast<const float4*>(&sW[ty * 32 + oo][i4 * 4]);
            acc[oo] = fmaf(w.x, r0, fmaf(w.y, r1, fmaf(w.z, r2, fmaf(w.w, r3, acc[oo]))));
        }
    }

#pragma unroll
    for (int oo = 0; oo < 32; oo++) {
        int o = o0 + ty * 32 + oo;
        g_fh[(size_t)o * 1024 + r * 128 + tx] = __float2half(acc[oo]);
    }
}

// ==================== kernel 3: HMMA GEMM, 2-term fp16 split ====================
// out[8192,3072] = Xh*Fh^T + Xl*Fh^T + bias
//
// BM=128, BN=128, BK=32, 3-stage cp.async pipeline, 2 CTAs/SM.
// smem per stage: Ah, Al, Bh each 128 rows x 64B (swizzled) = 3 x 8KB = 24KB.
// XOR swizzle: 16B-chunk c' = c ^ ((row>>1)&3) -> conflict-free for both
// cp.async stores and ldmatrix reads (validated in the passing R5 kernel).
static constexpr int BM = 128, BN = 128, BK = 32;
static constexpr int NCHUNKS = 1024 / BK;       // 32
static constexpr int STAGE_BYTES = 24576;
static constexpr int SMEM_SIZE = 3 * STAGE_BYTES;   // 73728 B -> 2 CTAs/SM fit

DINLINE uint32_t swz(int row, int chunk) {            // byte offset within one 8KB array
    return (uint32_t)(row * 64 + (chunk ^ ((row >> 1) & 3)) * 16);
}

DINLINE void load_stage(uint32_t sbase, int m0, int n0, int k0, int tid) {
    // 3 arrays x 128 rows x 4 chunks = 1536 cp.async / 256 threads = 6 each
#pragma unroll
    for (int t = 0; t < 6; t++) {
        int idx = tid + t * 256;
        int arr = idx >> 9;          // 0:Ah 1:Al 2:Bh
        int rem = idx & 511;
        int row = rem >> 2, chunk = rem & 3;
        const __half* src;
        if (arr == 0)      src = g_xh + (size_t)(m0 + row) * 1024 + k0 + chunk * 8;
        else if (arr == 1) src = g_xl + (size_t)(m0 + row) * 1024 + k0 + chunk * 8;
        else               src = g_fh + (size_t)(n0 + row) * 1024 + k0 + chunk * 8;
        cp_async16(sbase + arr * 8192 + swz(row, chunk), src);
    }
}

__global__ void __launch_bounds__(256, 2) gemm_kernel(
    const float* __restrict__ bias, float* __restrict__ out) {
    extern __shared__ __align__(128) char smem[];
    uint32_t sm0 = smem_u32(smem);

    int tid = threadIdx.x;
    int wid = tid >> 5, lane = tid & 31;
    int warp_m = wid & 1;                 // 2 warps in M
    int warp_n = wid >> 1;                // 4 warps in N
    int wm = warp_m * 64;                 // warp tile 64 x 32
    int wn = warp_n * 32;
    int m0 = blockIdx.x * BM;
    int n0 = blockIdx.y * BN;

    // per-lane ldmatrix row/half decomposition (same mapping as passing R5 kernel)
    int a_r    = lane & 15;               // A: lanes 0-15 -> k8-chunk 0, 16-31 -> chunk 1
    int a_half = lane >> 4;
    int b_r    = ((lane >> 4) << 3) | (lane & 7);  // B: n-row
    int b_half = (lane >> 3) & 1;                  // k half

    float acc[4][4][4];
#pragma unroll
    for (int i = 0; i < 4; i++)
#pragma unroll
        for (int j = 0; j < 4; j++)
#pragma unroll
            for (int q = 0; q < 4; q++) acc[i][j][q] = 0.0f;

    // prologue: stages 0, 1
    load_stage(sm0, m0, n0, 0, tid); cp_commit();
    load_stage(sm0 + STAGE_BYTES, m0, n0, BK, tid); cp_commit();

    for (int s = 0; s < NCHUNKS; s++) {
        if (s < NCHUNKS - 1) cp_wait1(); else cp_wait0();
        __syncthreads();

        if (s + 2 < NCHUNKS) {
            load_stage(sm0 + ((s + 2) % 3) * STAGE_BYTES, m0, n0, (s + 2) * BK, tid);
            cp_commit();
        }

        uint32_t sb = sm0 + (s % 3) * STAGE_BYTES;
        uint32_t sAh = sb, sAl = sb + 8192, sBh = sb + 16384;

#pragma unroll
        for (int kk = 0; kk < 2; kk++) {       // two k16 steps per 32-chunk
            int kb = kk * 2;                   // 16B-chunk base

            uint32_t bh[2][4];
#pragma unroll
            for (int nt = 0; nt < 2; nt++)
                ldsm4(bh[nt], sBh + swz(wn + nt * 16 + b_r, kb + b_half));

            // A fragments, double-buffered one mt ahead (limits live regs for occ=2)
            uint32_t ah[2][4], al[2][4];
            {
                uint32_t off = swz(wm + a_r, kb + a_half);
                ldsm4(ah[0], sAh + off);
                ldsm4(al[0], sAl + off);
            }
#pragma unroll
            for (int mt = 0; mt < 4; mt++) {
                int cur = mt & 1, nxt = cur ^ 1;
                if (mt < 3) {
                    uint32_t off = swz(wm + (mt + 1) * 16 + a_r, kb + a_half);
                    ldsm4(ah[nxt], sAh + off);
                    ldsm4(al[nxt], sAl + off);
                }
#pragma unroll
                for (int n8 = 0; n8 < 4; n8++) {
                    const uint32_t* pb = &bh[n8 >> 1][(n8 & 1) * 2];
                    mma_f16(acc[mt][n8], ah[cur], pb);   // Xh*Fh
                    mma_f16(acc[mt][n8], al[cur], pb);   // Xl*Fh
                }
            }
        }
    }

    // epilogue: C frag lane mapping: rows l/4, l/4+8; cols (l%4)*2, +1
    int cr = lane >> 2, cc = (lane & 3) * 2;
#pragma unroll
    for (int mt = 0; mt < 4; mt++) {
#pragma unroll
        for (int n8 = 0; n8 < 4; n8++) {
            int col = n0 + wn + n8 * 8 + cc;
            float b0 = __ldg(bias + col), b1 = __ldg(bias + col + 1);
            int row0 = m0 + wm + mt * 16 + cr;
            float2 v0 = make_float2(acc[mt][n8][0] + b0, acc[mt][n8][1] + b1);
            float2 v1 = make_float2(acc[mt][n8][2] + b0, acc[mt][n8][3] + b1);
            *reinterpret_cast<float2*>(out + (size_t)row0 * 3072 + col) = v0;
            *reinterpret_cast<float2*>(out + (size_t)(row0 + 8) * 3072 + col) = v1;
        }
    }
}

// ==================== host ====================
extern "C" void kernel_launch(void* const* d_in, const int* in_sizes, int n_in,
                              void* d_out, int out_size) {
    const float* attn = (const float*)d_in[0];   // [3072, 1024]
    const float* bias = (const float*)d_in[1];   // [3072]
    const float* x    = (const float*)d_in[2];   // [4, 2048, 1024]
    const float* qR   = (const float*)d_in[3];   // [8, 128, 128]
    const float* kR   = (const float*)d_in[4];
    const float* vR   = (const float*)d_in[5];
    float* out = (float*)d_out;                  // [8192, 3072]

    split_x_kernel<<<8192, 256>>>(reinterpret_cast<const float4*>(x));
    rotate_kernel<<<dim3(48, 8), dim3(128, 2)>>>(attn, qR, kR, vR);

    cudaFuncSetAttribute(gemm_kernel, cudaFuncAttributeMaxDynamicSharedMemorySize, SMEM_SIZE);
    gemm_kernel<<<dim3(64, 24), 256, SMEM_SIZE>>>(bias, out);
}

// round 7
// speedup vs baseline: 2.4208x; 1.5953x over previous
#include <cuda_runtime.h>
#include <cuda_fp16.h>
#include <cstdint>

#define DINLINE __device__ __forceinline__

// ---------------- device scratch (no dynamic alloc allowed) ----------------
static __device__ __align__(16) __half g_xh[8192 * 1024];
static __device__ __align__(16) __half g_fh[3072 * 1024];

// ---------------- portable PTX helpers (sm_80-class ISA only) ----------------
DINLINE uint32_t smem_u32(const void* p) {
    uint32_t a;
    asm("{ .reg .u64 t; cvta.to.shared.u64 t, %1; cvt.u32.u64 %0, t; }" : "=r"(a) : "l"(p));
    return a;
}
DINLINE void cp_async16(uint32_t dst, const void* src) {
    asm volatile("cp.async.cg.shared.global [%0], [%1], 16;" :: "r"(dst), "l"(src) : "memory");
}
DINLINE void cp_commit() { asm volatile("cp.async.commit_group;" ::: "memory"); }
DINLINE void cp_wait0() { asm volatile("cp.async.wait_group 0;" ::: "memory"); }
DINLINE void cp_wait1() { asm volatile("cp.async.wait_group 1;" ::: "memory"); }

DINLINE void ldsm4(uint32_t* r, uint32_t addr) {
    asm volatile("ldmatrix.sync.aligned.m8n8.x4.shared.b16 {%0,%1,%2,%3}, [%4];"
                 : "=r"(r[0]), "=r"(r[1]), "=r"(r[2]), "=r"(r[3]) : "r"(addr));
}
DINLINE void mma_f16(float* c, const uint32_t* a, const uint32_t* b) {
    asm volatile(
        "mma.sync.aligned.m16n8k16.row.col.f32.f16.f16.f32 "
        "{%0,%1,%2,%3}, {%4,%5,%6,%7}, {%8,%9}, {%0,%1,%2,%3};"
        : "+f"(c[0]), "+f"(c[1]), "+f"(c[2]), "+f"(c[3])
        : "r"(a[0]), "r"(a[1]), "r"(a[2]), "r"(a[3]), "r"(b[0]), "r"(b[1]));
}

DINLINE uint32_t pack_h2(__half a, __half b) {
    __half2 t = __halves2half2(a, b);
    return *reinterpret_cast<uint32_t*>(&t);
}

// ==================== kernel 1: convert x -> fp16 ====================
__global__ void __launch_bounds__(256) cvt_x_kernel(const float4* __restrict__ x4) {
    int i = blockIdx.x * 256 + threadIdx.x;   // 2,097,152 float4s total
    float4 v = x4[i];
    reinterpret_cast<uint2*>(g_xh)[i] =
        make_uint2(pack_h2(__float2half(v.x), __float2half(v.y)),
                   pack_h2(__float2half(v.z), __float2half(v.w)));
}

// ==================== kernel 2: rotate W -> filt, store fp16 ====================
// filt[o, r*128+j] = sum_i W[o, r*128+i] * R_sel[r, i, j]
__global__ void __launch_bounds__(256) rotate_kernel(
    const float* __restrict__ W, const float* __restrict__ qR,
    const float* __restrict__ kR, const float* __restrict__ vR) {
    __shared__ float sW[64][128];
    int o0 = blockIdx.x * 64;          // 48 o-tiles
    int r  = blockIdx.y;               // 8 blocks
    int tx = threadIdx.x;              // j: 0..127
    int ty = threadIdx.y;              // 0..1
    int tid = ty * 128 + tx;

    for (int idx = tid; idx < 64 * 128; idx += 256) {
        int row = idx >> 7, i = idx & 127;
        sW[row][i] = W[(size_t)(o0 + row) * 1024 + r * 128 + i];
    }
    __syncthreads();

    const float* R = ((o0 < 1024) ? qR : (o0 < 2048) ? kR : vR) + (size_t)r * 16384;

    float acc[32];
#pragma unroll
    for (int oo = 0; oo < 32; oo++) acc[oo] = 0.0f;

#pragma unroll 4
    for (int i4 = 0; i4 < 32; i4++) {
        float r0 = R[(i4 * 4 + 0) * 128 + tx];
        float r1 = R[(i4 * 4 + 1) * 128 + tx];
        float r2 = R[(i4 * 4 + 2) * 128 + tx];
        float r3 = R[(i4 * 4 + 3) * 128 + tx];
#pragma unroll
        for (int oo = 0; oo < 32; oo++) {
            float4 w = *reinterpret_cast<const float4*>(&sW[ty * 32 + oo][i4 * 4]);
            acc[oo] = fmaf(w.x, r0, fmaf(w.y, r1, fmaf(w.z, r2, fmaf(w.w, r3, acc[oo]))));
        }
    }

#pragma unroll
    for (int oo = 0; oo < 32; oo++) {
        int o = o0 + ty * 32 + oo;
        g_fh[(size_t)o * 1024 + r * 128 + tx] = __float2half(acc[oo]);
    }
}

// ==================== kernel 3: HMMA GEMM, single-term fp16 ====================
// out[8192,3072] = Xh*Fh^T + bias
//
// BM=128, BN=128, BK=64, 3-stage cp.async pipeline, 2 CTAs/SM.
// smem per stage: A, B each 128 rows x 128B (swizzled) = 2 x 16KB = 32KB.
// XOR swizzle on 128B rows: 16B-chunk c' = c ^ (row & 7) -> conflict-free for
// cp.async row writes (each warp covers whole rows) and ldmatrix 8-row phases.
static constexpr int BM = 128, BN = 128, BK = 64;
static constexpr int NCHUNKS = 1024 / BK;       // 16
static constexpr int STAGE_BYTES = 32768;
static constexpr int SMEM_SIZE = 3 * STAGE_BYTES;   // 96KB -> 2 CTAs/SM (192KB)

DINLINE uint32_t swz(int row, int chunk) {            // byte offset within one 16KB array
    return (uint32_t)(row * 128 + (chunk ^ (row & 7)) * 16);
}

DINLINE void load_stage(uint32_t sbase, int m0, int n0, int k0, int tid) {
    // 2 arrays x 128 rows x 8 chunks = 2048 cp.async / 256 threads = 8 each
#pragma unroll
    for (int t = 0; t < 8; t++) {
        int idx = tid + t * 256;
        int arr = idx >> 10;         // 0:A 1:B
        int rem = idx & 1023;
        int row = rem >> 3, chunk = rem & 7;
        const __half* src = (arr == 0)
            ? g_xh + (size_t)(m0 + row) * 1024 + k0 + chunk * 8
            : g_fh + (size_t)(n0 + row) * 1024 + k0 + chunk * 8;
        cp_async16(sbase + arr * 16384 + swz(row, chunk), src);
    }
}

__global__ void __launch_bounds__(256, 2) gemm_kernel(
    const float* __restrict__ bias, float* __restrict__ out) {
    extern __shared__ __align__(128) char smem[];
    uint32_t sm0 = smem_u32(smem);

    int tid = threadIdx.x;
    int wid = tid >> 5, lane = tid & 31;
    int warp_m = wid & 1;                 // 2 warps in M
    int warp_n = wid >> 1;                // 4 warps in N
    int wm = warp_m * 64;                 // warp tile 64 x 32
    int wn = warp_n * 32;
    int m0 = blockIdx.x * BM;
    int n0 = blockIdx.y * BN;

    // per-lane ldmatrix row/half decomposition (validated mapping)
    int a_r    = lane & 15;               // A rows; lanes 16-31 -> k8 half 1
    int a_half = lane >> 4;
    int b_r    = ((lane >> 4) << 3) | (lane & 7);  // B: n-row
    int b_half = (lane >> 3) & 1;                  // k half

    float acc[4][4][4];
#pragma unroll
    for (int i = 0; i < 4; i++)
#pragma unroll
        for (int j = 0; j < 4; j++)
#pragma unroll
            for (int q = 0; q < 4; q++) acc[i][j][q] = 0.0f;

    // prologue: stages 0, 1
    load_stage(sm0, m0, n0, 0, tid); cp_commit();
    load_stage(sm0 + STAGE_BYTES, m0, n0, BK, tid); cp_commit();

    for (int s = 0; s < NCHUNKS; s++) {
        if (s < NCHUNKS - 1) cp_wait1(); else cp_wait0();
        __syncthreads();

        if (s + 2 < NCHUNKS) {
            load_stage(sm0 + ((s + 2) % 3) * STAGE_BYTES, m0, n0, (s + 2) * BK, tid);
            cp_commit();
        }

        uint32_t sb = sm0 + (s % 3) * STAGE_BYTES;
        uint32_t sA = sb, sB = sb + 16384;

#pragma unroll
        for (int kk = 0; kk < 4; kk++) {       // four k16 steps per 64-chunk
            int kb = kk * 2;                   // 16B-chunk base (2 chunks per k16)

            uint32_t bh[2][4];
#pragma unroll
            for (int nt = 0; nt < 2; nt++)
                ldsm4(bh[nt], sB + swz(wn + nt * 16 + b_r, kb + b_half));

            // A fragments, double-buffered one mt ahead
            uint32_t ah[2][4];
            ldsm4(ah[0], sA + swz(wm + a_r, kb + a_half));
#pragma unroll
            for (int mt = 0; mt < 4; mt++) {
                int cur = mt & 1, nxt = cur ^ 1;
                if (mt < 3)
                    ldsm4(ah[nxt], sA + swz(wm + (mt + 1) * 16 + a_r, kb + a_half));
#pragma unroll
                for (int n8 = 0; n8 < 4; n8++) {
                    const uint32_t* pb = &bh[n8 >> 1][(n8 & 1) * 2];
                    mma_f16(acc[mt][n8], ah[cur], pb);
                }
            }
        }
    }

    // epilogue: C frag lane mapping: rows l/4, l/4+8; cols (l%4)*2, +1
    int cr = lane >> 2, cc = (lane & 3) * 2;
#pragma unroll
    for (int mt = 0; mt < 4; mt++) {
#pragma unroll
        for (int n8 = 0; n8 < 4; n8++) {
            int col = n0 + wn + n8 * 8 + cc;
            float b0 = __ldg(bias + col), b1 = __ldg(bias + col + 1);
            int row0 = m0 + wm + mt * 16 + cr;
            float2 v0 = make_float2(acc[mt][n8][0] + b0, acc[mt][n8][1] + b1);
            float2 v1 = make_float2(acc[mt][n8][2] + b0, acc[mt][n8][3] + b1);
            *reinterpret_cast<float2*>(out + (size_t)row0 * 3072 + col) = v0;
            *reinterpret_cast<float2*>(out + (size_t)(row0 + 8) * 3072 + col) = v1;
        }
    }
}

// ==================== host ====================
extern "C" void kernel_launch(void* const* d_in, const int* in_sizes, int n_in,
                              void* d_out, int out_size) {
    const float* attn = (const float*)d_in[0];   // [3072, 1024]
    const float* bias = (const float*)d_in[1];   // [3072]
    const float* x    = (const float*)d_in[2];   // [4, 2048, 1024]
    const float* qR   = (const float*)d_in[3];   // [8, 128, 128]
    const float* kR   = (const float*)d_in[4];
    const float* vR   = (const float*)d_in[5];
    float* out = (float*)d_out;                  // [8192, 3072]

    cvt_x_kernel<<<8192, 256>>>(reinterpret_cast<const float4*>(x));
    rotate_kernel<<<dim3(48, 8), dim3(128, 2)>>>(attn, qR, kR, vR);

    cudaFuncSetAttribute(gemm_kernel, cudaFuncAttributeMaxDynamicSharedMemorySize, SMEM_SIZE);
    gemm_kernel<<<dim3(64, 24), 256, SMEM_SIZE>>>(bias, out);
}